// round 13
// baseline (speedup 1.0000x reference)
#include <cuda_runtime.h>
#include <cstdint>

// Problem constants: B=16, H=8, R=400, F=256, dilated 2^k = 8
#define BH    128
#define RDIM  400
#define FDIM  256
#define NROWS (BH * RDIM)   // 51200

// Scratch
__device__ float    g_agg[(size_t)NROWS * FDIM];   // tf32-rounded agg
__device__ float    g_Wt[FDIM * FDIM];             // tf32-rounded W
__device__ uint32_t g_meta[(size_t)NROWS * 16];    // per row: p[7], pad, v[7], pad

// ---------------------------------------------------------------------------
// helpers
// ---------------------------------------------------------------------------
__device__ __forceinline__ uint32_t smem_u32(const void* p) {
    uint32_t a;
    asm("{ .reg .u64 t; cvta.to.shared.u64 t, %1; cvt.u32.u64 %0, t; }"
        : "=r"(a) : "l"(p));
    return a;
}

__device__ __forceinline__ float f2tf32(float x) {
    uint32_t r;
    asm("cvt.rna.tf32.f32 %0, %1;" : "=r"(r) : "f"(x));
    return __uint_as_float(r);
}

__device__ __forceinline__ void ldsm_x4(uint32_t r[4], uint32_t addr) {
    asm volatile("ldmatrix.sync.aligned.m8n8.x4.shared.b16 {%0,%1,%2,%3}, [%4];"
                 : "=r"(r[0]), "=r"(r[1]), "=r"(r[2]), "=r"(r[3]) : "r"(addr));
}

__device__ __forceinline__ void mma_tf32(float c[4], const uint32_t a[4],
                                         const uint32_t b0, const uint32_t b1) {
    asm volatile(
        "mma.sync.aligned.m16n8k8.row.col.f32.tf32.tf32.f32 "
        "{%0,%1,%2,%3}, {%4,%5,%6,%7}, {%8,%9}, {%0,%1,%2,%3};"
        : "+f"(c[0]), "+f"(c[1]), "+f"(c[2]), "+f"(c[3])
        : "r"(a[0]), "r"(a[1]), "r"(a[2]), "r"(a[3]), "r"(b0), "r"(b1));
}

__device__ __forceinline__ void cp_async16(uint32_t saddr, const void* gaddr) {
    asm volatile("cp.async.cg.shared.global [%0], [%1], 16;"
                 :: "r"(saddr), "l"(gaddr));
}
#define CP_COMMIT() asm volatile("cp.async.commit_group;")
#define CP_WAIT(N)  asm volatile("cp.async.wait_group %0;" :: "n"(N))

// ---------------------------------------------------------------------------
// Kernel 1: ranks only. TWO rows per warp, no smem, no block barriers.
// Writes per-row meta: positions p[0..6] and values v[0..6] (v[6]=0 if the
// diagonal already appears among the 6 rank positions -> branch-free gather).
// Tail 64 blocks convert W -> tf32 (rna) into g_Wt.
// ---------------------------------------------------------------------------
__global__ __launch_bounds__(256) void rank_kernel(
    const float* __restrict__ A,
    const float* __restrict__ W,
    float* __restrict__ Wt,
    uint32_t* __restrict__ meta)
{
    if (blockIdx.x >= NROWS / 16) {
        int i = (blockIdx.x - NROWS / 16) * 256 + threadIdx.x;
        float4 w = reinterpret_cast<const float4*>(W)[i];
        w.x = f2tf32(w.x); w.y = f2tf32(w.y);
        w.z = f2tf32(w.z); w.w = f2tf32(w.w);
        reinterpret_cast<float4*>(Wt)[i] = w;
        return;
    }

    const int lid  = threadIdx.x & 31;
    const int wid  = threadIdx.x >> 5;
    const int row0 = blockIdx.x * 16 + wid * 2;

    const float* ar0 = A + (size_t)row0 * RDIM;
    const float* ar1 = ar0 + RDIM;
    const float4* a40 = reinterpret_cast<const float4*>(ar0);
    const float4* a41 = reinterpret_cast<const float4*>(ar1);

    float v[2][6];
    #pragma unroll
    for (int rr = 0; rr < 2; rr++) {
        const float* ar = rr ? ar1 : ar0;
        v[rr][0] = __ldg(ar + 0);
        v[rr][1] = __ldg(ar + 8);
        v[rr][2] = __ldg(ar + 9);
        v[rr][3] = __ldg(ar + 10);
        v[rr][4] = __ldg(ar + 11);
        v[rr][5] = __ldg(ar + 12);
    }

    int cnt[2][6];
    #pragma unroll
    for (int rr = 0; rr < 2; rr++)
        #pragma unroll
        for (int k = 0; k < 6; k++) cnt[rr][k] = 0;

    // iteration 0 (j = 4*lid < 128): full stable tie-break logic
    {
        const int j = lid * 4;
        float4 f0 = __ldg(a40 + lid);
        float4 f1 = __ldg(a41 + lid);
        #pragma unroll
        for (int rr = 0; rr < 2; rr++) {
            float4 f = rr ? f1 : f0;
            cnt[rr][0] += (f.x > v[rr][0]) + (f.y > v[rr][0])
                        + (f.z > v[rr][0]) + (f.w > v[rr][0]);
            #pragma unroll
            for (int k = 1; k < 6; k++) {
                const int thr = 7 + k;   // 8..12
                cnt[rr][k] +=
                      ((f.x > v[rr][k]) | ((f.x == v[rr][k]) & (j     < thr)))
                    + ((f.y > v[rr][k]) | ((f.y == v[rr][k]) & (j + 1 < thr)))
                    + ((f.z > v[rr][k]) | ((f.z == v[rr][k]) & (j + 2 < thr)))
                    + ((f.w > v[rr][k]) | ((f.w == v[rr][k]) & (j + 3 < thr)));
            }
        }
    }
    // remaining iterations: j >= 128 > 12 -> pure greater-than counts
    for (int q = lid + 32; q < RDIM / 4; q += 32) {
        float4 f0 = __ldg(a40 + q);
        float4 f1 = __ldg(a41 + q);
        #pragma unroll
        for (int rr = 0; rr < 2; rr++) {
            float4 f = rr ? f1 : f0;
            #pragma unroll
            for (int k = 0; k < 6; k++)
                cnt[rr][k] += (f.x > v[rr][k]) + (f.y > v[rr][k])
                            + (f.z > v[rr][k]) + (f.w > v[rr][k]);
        }
    }

    #pragma unroll
    for (int rr = 0; rr < 2; rr++) {
        int p[7];
        #pragma unroll
        for (int k = 0; k < 6; k++)
            p[k] = (int)__reduce_add_sync(0xffffffffu, (unsigned)cnt[rr][k]);
        const int row = row0 + rr;
        const int i   = row - (row / RDIM) * RDIM;
        p[6] = i;
        bool diag = (p[0] == i) | (p[1] == i) | (p[2] == i)
                  | (p[3] == i) | (p[4] == i) | (p[5] == i);

        const float* ar = rr ? ar1 : ar0;
        float pv[7];
        #pragma unroll
        for (int m = 0; m < 7; m++) pv[m] = __ldg(ar + p[m]);
        if (diag) pv[6] = 0.f;   // diagonal already counted -> zero weight

        if (lid == rr) {         // lane rr writes row rr's meta (64 B)
            uint4* dst = reinterpret_cast<uint4*>(meta + (size_t)row * 16);
            dst[0] = make_uint4(p[0], p[1], p[2], p[3]);
            dst[1] = make_uint4(p[4], p[5], p[6], 0u);
            dst[2] = make_uint4(__float_as_uint(pv[0]), __float_as_uint(pv[1]),
                                __float_as_uint(pv[2]), __float_as_uint(pv[3]));
            dst[3] = make_uint4(__float_as_uint(pv[4]), __float_as_uint(pv[5]),
                                __float_as_uint(pv[6]), 0u);
        }
    }
}

// ---------------------------------------------------------------------------
// Kernel 1b: gather. One CTA per (bh, F-half). Stages the 400x128 feats
// slice-half (200 KB) in smem; the 7x gather reuse is served from smem
// instead of L2. Branch-free 7-term FMA per output element; agg tf32-rounded.
// ---------------------------------------------------------------------------
#define GATHER_SMEM (RDIM * 32 * 16)   // 400 rows * 32 float4 = 204800 B

__global__ __launch_bounds__(512) void gather_kernel(
    const float* __restrict__ feats,
    const uint32_t* __restrict__ meta,
    float* __restrict__ agg)
{
    extern __shared__ float4 sm4[];    // [400][32]
    const int b    = blockIdx.x;       // 0..255
    const int bh   = b >> 1;
    const int half = b & 1;
    const int t    = threadIdx.x;
    const int w    = t >> 5;           // 0..15
    const int lid  = t & 31;

    const float4* fb = reinterpret_cast<const float4*>(feats)
                     + (size_t)bh * RDIM * (FDIM / 4) + half * 32;

    // stage slice-half: warp w loads rows w, w+16, ... (25 rows each)
    for (int r = w; r < RDIM; r += 16)
        sm4[r * 32 + lid] = __ldg(fb + (size_t)r * (FDIM / 4) + lid);
    __syncthreads();

    float4* ag = reinterpret_cast<float4*>(agg) + half * 32;
    const uint32_t* mbase = meta + (size_t)bh * RDIM * 16;

    for (int r = w; r < RDIM; r += 16) {
        const uint32_t* mt = mbase + (size_t)r * 16;
        // warp-uniform scalar loads (single wavefront each, L1-cached)
        int   p0 = __ldg((const int*)mt + 0), p1 = __ldg((const int*)mt + 1);
        int   p2 = __ldg((const int*)mt + 2), p3 = __ldg((const int*)mt + 3);
        int   p4 = __ldg((const int*)mt + 4), p5 = __ldg((const int*)mt + 5);
        int   p6 = __ldg((const int*)mt + 6);
        float v0 = __uint_as_float(__ldg(mt + 8));
        float v1 = __uint_as_float(__ldg(mt + 9));
        float v2 = __uint_as_float(__ldg(mt + 10));
        float v3 = __uint_as_float(__ldg(mt + 11));
        float v4 = __uint_as_float(__ldg(mt + 12));
        float v5 = __uint_as_float(__ldg(mt + 13));
        float v6 = __uint_as_float(__ldg(mt + 14));

        float4 f, acc = make_float4(0.f, 0.f, 0.f, 0.f);
        #define ACC(pp, vv) \
            f = sm4[(pp) * 32 + lid]; \
            acc.x += (vv) * f.x; acc.y += (vv) * f.y; \
            acc.z += (vv) * f.z; acc.w += (vv) * f.w;
        ACC(p0, v0) ACC(p1, v1) ACC(p2, v2) ACC(p3, v3)
        ACC(p4, v4) ACC(p5, v5) ACC(p6, v6)
        #undef ACC

        acc.x = f2tf32(acc.x); acc.y = f2tf32(acc.y);
        acc.z = f2tf32(acc.z); acc.w = f2tf32(acc.w);
        ag[(size_t)(bh * RDIM + r) * (FDIM / 4) + lid] = acc;
    }
}

// ---------------------------------------------------------------------------
// Kernel 2: out = relu(agg @ W^T + b) + feats via mma.sync tf32 (m16n8k8).
// (verbatim from round-12: 128x128 tile, BK=32, 3-stage cp.async)
// ---------------------------------------------------------------------------
#define MT 128
#define NT 128
#define BK 32
#define NCHUNK (FDIM / BK)      // 8
#define RS 36
#define STAGE_FLOATS (2 * MT * RS)
#define NSTAGE 3
#define SMEM_FLOATS  (NSTAGE * STAGE_FLOATS)  // 110592 B
#define EPS 132

extern __shared__ float sm_dyn[];

__global__ __launch_bounds__(256, 2) void gemm_tf32_kernel(
    const float* __restrict__ agg,
    const float* __restrict__ Wt,
    const float* __restrict__ bias,
    const float* __restrict__ feats,
    float* __restrict__ out)
{
    const int t   = threadIdx.x;
    const int wid = t >> 5;
    const int lid = t & 31;
    const int m0  = blockIdx.y * MT;
    const int n0  = blockIdx.x * NT;
    const int wm  = wid & 3;
    const int wn  = wid >> 2;

    const uint32_t sb = smem_u32(sm_dyn);

    const uint32_t aAddrBase = sb +
        ((uint32_t)((wm * 32 + ((lid >> 3) & 1) * 8 + (lid & 7)) * RS
                    + (lid >> 4) * 4) << 2);
    const uint32_t bAddrBase = sb + (uint32_t)(MT * RS * 4) +
        ((uint32_t)((wn * 64 + (lid >> 4) * 8 + (lid & 7)) * RS
                    + ((lid >> 3) & 1) * 4) << 2);

    float acc[2][8][4];
    #pragma unroll
    for (int a = 0; a < 2; a++)
        #pragma unroll
        for (int j = 0; j < 8; j++)
            #pragma unroll
            for (int k = 0; k < 4; k++) acc[a][j][k] = 0.f;

    auto issue_chunk = [&](int c, int stage) {
        const uint32_t sbase = sb + (uint32_t)(stage * STAGE_FLOATS * 4);
        #pragma unroll
        for (int u = 0; u < 8; u++) {
            int idx = u * 256 + t;
            int e   = idx & 1023;
            int r   = e >> 3;
            int c4  = e & 7;
            uint32_t sd;
            const float* gs;
            if (idx < 1024) {
                sd = sbase + (uint32_t)((r * RS + c4 * 4) << 2);
                gs = agg + (size_t)(m0 + r) * FDIM + c * BK + c4 * 4;
            } else {
                sd = sbase + (uint32_t)(MT * RS * 4) + (uint32_t)((r * RS + c4 * 4) << 2);
                gs = Wt + (size_t)(n0 + r) * FDIM + c * BK + c4 * 4;
            }
            cp_async16(sd, gs);
        }
        CP_COMMIT();
    };

    issue_chunk(0, 0);
    issue_chunk(1, 1);
    CP_WAIT(1);
    __syncthreads();

    #pragma unroll 1
    for (int c = 0; c < NCHUNK; c++) {
        const int stage = c % NSTAGE;
        const uint32_t aS = aAddrBase + (uint32_t)(stage * STAGE_FLOATS * 4);
        const uint32_t bS = bAddrBase + (uint32_t)(stage * STAGE_FLOATS * 4);

        #pragma unroll
        for (int ks = 0; ks < 4; ks++) {
            uint32_t afr[2][4];
            #pragma unroll
            for (int tm = 0; tm < 2; tm++)
                ldsm_x4(afr[tm], aS + (uint32_t)((tm * 16 * RS + ks * 8) << 2));

            uint32_t bfr[4][4];
            #pragma unroll
            for (int jj = 0; jj < 4; jj++)
                ldsm_x4(bfr[jj], bS + (uint32_t)((jj * 16 * RS + ks * 8) << 2));

            #pragma unroll
            for (int tm = 0; tm < 2; tm++)
                #pragma unroll
                for (int j = 0; j < 8; j++)
                    mma_tf32(acc[tm][j], afr[tm], bfr[j >> 1][(j & 1) * 2],
                             bfr[j >> 1][(j & 1) * 2 + 1]);
        }

        if (c + 2 < NCHUNK) {
            issue_chunk(c + 2, (c + 2) % NSTAGE);
            CP_WAIT(1);
            __syncthreads();
        } else if (c + 1 < NCHUNK) {
            CP_WAIT(0);
            __syncthreads();
        }
    }
    __syncthreads();

    {
        float* ep = sm_dyn;
        #pragma unroll
        for (int tm = 0; tm < 2; tm++) {
            int rbase = wm * 32 + tm * 16 + (lid >> 2);
            int cbase = wn * 64 + (lid & 3) * 2;
            #pragma unroll
            for (int j = 0; j < 8; j++) {
                float2 lo = make_float2(acc[tm][j][0], acc[tm][j][1]);
                float2 hi = make_float2(acc[tm][j][2], acc[tm][j][3]);
                *reinterpret_cast<float2*>(&ep[rbase * EPS + cbase + j * 8])       = lo;
                *reinterpret_cast<float2*>(&ep[(rbase + 8) * EPS + cbase + j * 8]) = hi;
            }
        }
        __syncthreads();

        const float4* f4 = reinterpret_cast<const float4*>(feats);
        float4* o4 = reinterpret_cast<float4*>(out);
        const float4* b4 = reinterpret_cast<const float4*>(bias);
        #pragma unroll
        for (int it = 0; it < 16; it++) {
            int lin = it * 256 + t;
            int r   = lin >> 5;
            int c4  = lin & 31;
            float4 v = *reinterpret_cast<const float4*>(&ep[r * EPS + c4 * 4]);
            float4 bb = __ldg(&b4[(n0 >> 2) + c4]);
            size_t gi = ((size_t)(m0 + r) * FDIM + n0) / 4 + c4;
            float4 ff = __ldg(&f4[gi]);
            v.x = fmaxf(v.x + bb.x, 0.f) + ff.x;
            v.y = fmaxf(v.y + bb.y, 0.f) + ff.y;
            v.z = fmaxf(v.z + bb.z, 0.f) + ff.z;
            v.w = fmaxf(v.w + bb.w, 0.f) + ff.w;
            o4[gi] = v;
        }
    }
}

// ---------------------------------------------------------------------------
extern "C" void kernel_launch(void* const* d_in, const int* in_sizes, int n_in,
                              void* d_out, int out_size)
{
    const float* A     = (const float*)d_in[0];  // [16,8,400,400]
    const float* feats = (const float*)d_in[1];  // [16,8,400,256]
    const float* W     = (const float*)d_in[2];  // [256,256]
    const float* bias  = (const float*)d_in[3];  // [256]
    float* out = (float*)d_out;

    float*    agg;  cudaGetSymbolAddress((void**)&agg,  g_agg);
    float*    Wt;   cudaGetSymbolAddress((void**)&Wt,   g_Wt);
    uint32_t* meta; cudaGetSymbolAddress((void**)&meta, g_meta);

    static bool attr_set = false;
    if (!attr_set) {
        cudaFuncSetAttribute(gemm_tf32_kernel,
                             cudaFuncAttributeMaxDynamicSharedMemorySize,
                             SMEM_FLOATS * 4);
        cudaFuncSetAttribute(gather_kernel,
                             cudaFuncAttributeMaxDynamicSharedMemorySize,
                             GATHER_SMEM);
        attr_set = true;
    }

    rank_kernel<<<NROWS / 16 + 64, 256>>>(A, W, Wt, meta);
    gather_kernel<<<BH * 2, 512, GATHER_SMEM>>>(feats, meta, agg);

    dim3 grid(FDIM / NT, NROWS / MT);   // (2, 400)
    gemm_tf32_kernel<<<grid, 256, SMEM_FLOATS * 4>>>(agg, Wt, bias, feats, out);
}

// round 14
// speedup vs baseline: 1.2791x; 1.2791x over previous
#include <cuda_runtime.h>
#include <cstdint>

// Problem constants: B=16, H=8, R=400, F=256, dilated 2^k = 8
#define BH    128
#define RDIM  400
#define FDIM  256
#define NROWS (BH * RDIM)   // 51200

// Scratch: agg (tf32-rounded fp32 bits) [NROWS, FDIM] = 52.4 MB, W tf32 copy
__device__ float g_agg[(size_t)NROWS * FDIM];
__device__ float g_Wt[FDIM * FDIM];

// ---------------------------------------------------------------------------
// helpers
// ---------------------------------------------------------------------------
__device__ __forceinline__ uint32_t smem_u32(const void* p) {
    uint32_t a;
    asm("{ .reg .u64 t; cvta.to.shared.u64 t, %1; cvt.u32.u64 %0, t; }"
        : "=r"(a) : "l"(p));
    return a;
}

__device__ __forceinline__ float f2tf32(float x) {
    uint32_t r;
    asm("cvt.rna.tf32.f32 %0, %1;" : "=r"(r) : "f"(x));
    return __uint_as_float(r);
}

__device__ __forceinline__ void ldsm_x4(uint32_t r[4], uint32_t addr) {
    asm volatile("ldmatrix.sync.aligned.m8n8.x4.shared.b16 {%0,%1,%2,%3}, [%4];"
                 : "=r"(r[0]), "=r"(r[1]), "=r"(r[2]), "=r"(r[3]) : "r"(addr));
}

__device__ __forceinline__ void mma_tf32(float c[4], const uint32_t a[4],
                                         const uint32_t b0, const uint32_t b1) {
    asm volatile(
        "mma.sync.aligned.m16n8k8.row.col.f32.tf32.tf32.f32 "
        "{%0,%1,%2,%3}, {%4,%5,%6,%7}, {%8,%9}, {%0,%1,%2,%3};"
        : "+f"(c[0]), "+f"(c[1]), "+f"(c[2]), "+f"(c[3])
        : "r"(a[0]), "r"(a[1]), "r"(a[2]), "r"(a[3]), "r"(b0), "r"(b1));
}

__device__ __forceinline__ void cp_async16(uint32_t saddr, const void* gaddr) {
    asm volatile("cp.async.cg.shared.global [%0], [%1], 16;"
                 :: "r"(saddr), "l"(gaddr));
}
#define CP_COMMIT() asm volatile("cp.async.commit_group;")
#define CP_WAIT(N)  asm volatile("cp.async.wait_group %0;" :: "n"(N))

// ---------------------------------------------------------------------------
// Kernel 1: mask + sparse gather (verbatim round-12, 101us best config).
// TWO rows per warp, no smem, no block barriers. Tie-break ALU only in the
// first strip iteration. Tail 64 blocks convert W -> tf32 (rna) into g_Wt.
// ---------------------------------------------------------------------------
__global__ __launch_bounds__(256) void mask_agg_kernel(
    const float* __restrict__ A,
    const float* __restrict__ feats,
    const float* __restrict__ W,
    float* __restrict__ Wt,
    float* __restrict__ agg)
{
    if (blockIdx.x >= NROWS / 16) {
        int i = (blockIdx.x - NROWS / 16) * 256 + threadIdx.x;
        float4 w = reinterpret_cast<const float4*>(W)[i];
        w.x = f2tf32(w.x); w.y = f2tf32(w.y);
        w.z = f2tf32(w.z); w.w = f2tf32(w.w);
        reinterpret_cast<float4*>(Wt)[i] = w;
        return;
    }

    const int lid  = threadIdx.x & 31;
    const int wid  = threadIdx.x >> 5;
    const int row0 = blockIdx.x * 16 + wid * 2;

    const float* ar0 = A + (size_t)row0 * RDIM;
    const float* ar1 = ar0 + RDIM;
    const float4* a40 = reinterpret_cast<const float4*>(ar0);
    const float4* a41 = reinterpret_cast<const float4*>(ar1);

    float v[2][6];
    #pragma unroll
    for (int rr = 0; rr < 2; rr++) {
        const float* ar = rr ? ar1 : ar0;
        v[rr][0] = __ldg(ar + 0);
        v[rr][1] = __ldg(ar + 8);
        v[rr][2] = __ldg(ar + 9);
        v[rr][3] = __ldg(ar + 10);
        v[rr][4] = __ldg(ar + 11);
        v[rr][5] = __ldg(ar + 12);
    }

    int cnt[2][6];
    #pragma unroll
    for (int rr = 0; rr < 2; rr++)
        #pragma unroll
        for (int k = 0; k < 6; k++) cnt[rr][k] = 0;

    // iteration 0 (j = 4*lid < 128): full stable tie-break logic
    {
        const int j = lid * 4;
        float4 f0 = __ldg(a40 + lid);
        float4 f1 = __ldg(a41 + lid);
        #pragma unroll
        for (int rr = 0; rr < 2; rr++) {
            float4 f = rr ? f1 : f0;
            cnt[rr][0] += (f.x > v[rr][0]) + (f.y > v[rr][0])
                        + (f.z > v[rr][0]) + (f.w > v[rr][0]);
            #pragma unroll
            for (int k = 1; k < 6; k++) {
                const int thr = 7 + k;   // 8..12
                cnt[rr][k] +=
                      ((f.x > v[rr][k]) | ((f.x == v[rr][k]) & (j     < thr)))
                    + ((f.y > v[rr][k]) | ((f.y == v[rr][k]) & (j + 1 < thr)))
                    + ((f.z > v[rr][k]) | ((f.z == v[rr][k]) & (j + 2 < thr)))
                    + ((f.w > v[rr][k]) | ((f.w == v[rr][k]) & (j + 3 < thr)));
            }
        }
    }
    // remaining iterations: j >= 128 > 12 -> pure greater-than counts
    for (int q = lid + 32; q < RDIM / 4; q += 32) {
        float4 f0 = __ldg(a40 + q);
        float4 f1 = __ldg(a41 + q);
        #pragma unroll
        for (int rr = 0; rr < 2; rr++) {
            float4 f = rr ? f1 : f0;
            #pragma unroll
            for (int k = 0; k < 6; k++)
                cnt[rr][k] += (f.x > v[rr][k]) + (f.y > v[rr][k])
                            + (f.z > v[rr][k]) + (f.w > v[rr][k]);
        }
    }

    int   p[2][7];
    float val[2][7];
    int   n[2];
    #pragma unroll
    for (int rr = 0; rr < 2; rr++) {
        #pragma unroll
        for (int k = 0; k < 6; k++)
            p[rr][k] = (int)__reduce_add_sync(0xffffffffu, (unsigned)cnt[rr][k]);
        const int row = row0 + rr;
        const int i   = row - (row / RDIM) * RDIM;
        p[rr][6] = i;
        bool diag = (p[rr][0] == i) | (p[rr][1] == i) | (p[rr][2] == i)
                  | (p[rr][3] == i) | (p[rr][4] == i) | (p[rr][5] == i);
        n[rr] = diag ? 6 : 7;
        const float* ar = rr ? ar1 : ar0;
        #pragma unroll
        for (int m = 0; m < 7; m++) val[rr][m] = __ldg(ar + p[rr][m]);
    }

    float4 acc[2][2];
    #pragma unroll
    for (int rr = 0; rr < 2; rr++) {
        acc[rr][0] = make_float4(0.f, 0.f, 0.f, 0.f);
        acc[rr][1] = make_float4(0.f, 0.f, 0.f, 0.f);
    }

    #pragma unroll
    for (int m = 0; m < 7; m++) {
        #pragma unroll
        for (int rr = 0; rr < 2; rr++) {
            if (m < n[rr]) {
                const int row = row0 + rr;
                const int bh  = row / RDIM;
                const float4* fb = reinterpret_cast<const float4*>(
                    feats + (size_t)bh * RDIM * FDIM);
                const float w = val[rr][m];
                const float4* src = fb + (size_t)p[rr][m] * (FDIM / 4) + lid * 2;
                float4 f0 = __ldg(src);
                float4 f1 = __ldg(src + 1);
                acc[rr][0].x += w * f0.x; acc[rr][0].y += w * f0.y;
                acc[rr][0].z += w * f0.z; acc[rr][0].w += w * f0.w;
                acc[rr][1].x += w * f1.x; acc[rr][1].y += w * f1.y;
                acc[rr][1].z += w * f1.z; acc[rr][1].w += w * f1.w;
            }
        }
    }

    #pragma unroll
    for (int rr = 0; rr < 2; rr++) {
        float4 a0 = acc[rr][0], a1 = acc[rr][1];
        a0.x = f2tf32(a0.x); a0.y = f2tf32(a0.y);
        a0.z = f2tf32(a0.z); a0.w = f2tf32(a0.w);
        a1.x = f2tf32(a1.x); a1.y = f2tf32(a1.y);
        a1.z = f2tf32(a1.z); a1.w = f2tf32(a1.w);
        float4* ao = reinterpret_cast<float4*>(
            agg + (size_t)(row0 + rr) * FDIM) + lid * 2;
        ao[0] = a0;
        ao[1] = a1;
    }
}

// ---------------------------------------------------------------------------
// Kernel 2: out = relu(agg @ W^T + b) + feats via mma.sync tf32 (m16n8k8).
// CTA tile 128x64 (was 128x128) -> acc 32 regs -> 3 CTAs/SM (24 warps).
// 8 warps in 4(M)x2(N), warp tile 32x32. 2-stage cp.async, BK=32.
// Grid (4,400): 4 N-tiles of an M-tile are bid-adjacent -> agg L2 reuse.
// ---------------------------------------------------------------------------
#define MT 128
#define NT 64
#define BK 32
#define NCHUNK (FDIM / BK)      // 8
#define RS 36                   // smem row stride (floats)
#define STAGE_FLOATS ((MT + NT) * RS)       // 6912 floats = 27648 B
#define NSTAGE 2
#define SMEM_FLOATS  (NSTAGE * STAGE_FLOATS)  // 13824 floats = 55296 B
#define EPS 68                  // epilogue row stride (floats)

extern __shared__ float sm_dyn[];

__global__ __launch_bounds__(256, 3) void gemm_tf32_kernel(
    const float* __restrict__ agg,
    const float* __restrict__ Wt,
    const float* __restrict__ bias,
    const float* __restrict__ feats,
    float* __restrict__ out)
{
    const int t   = threadIdx.x;
    const int wid = t >> 5;
    const int lid = t & 31;
    const int m0  = blockIdx.y * MT;
    const int n0  = blockIdx.x * NT;
    const int wm  = wid & 3;        // warp M index (0..3), 32 rows each
    const int wn  = wid >> 2;       // warp N index (0..1), 32 cols each

    const uint32_t sb = smem_u32(sm_dyn);

    const uint32_t aAddrBase = sb +
        ((uint32_t)((wm * 32 + ((lid >> 3) & 1) * 8 + (lid & 7)) * RS
                    + (lid >> 4) * 4) << 2);
    const uint32_t bAddrBase = sb + (uint32_t)(MT * RS * 4) +
        ((uint32_t)((wn * 32 + (lid >> 4) * 8 + (lid & 7)) * RS
                    + ((lid >> 3) & 1) * 4) << 2);

    float acc[2][4][4];
    #pragma unroll
    for (int a = 0; a < 2; a++)
        #pragma unroll
        for (int j = 0; j < 4; j++)
            #pragma unroll
            for (int k = 0; k < 4; k++) acc[a][j][k] = 0.f;

    // 1536 float4-elements per chunk: first 1024 -> A tile, next 512 -> B tile
    auto issue_chunk = [&](int c, int stage) {
        const uint32_t sbase = sb + (uint32_t)(stage * STAGE_FLOATS * 4);
        #pragma unroll
        for (int u = 0; u < 6; u++) {
            int idx = u * 256 + t;          // 0..1535
            uint32_t sd;
            const float* gs;
            if (idx < 1024) {
                int r = idx >> 3, c4 = idx & 7;
                sd = sbase + (uint32_t)((r * RS + c4 * 4) << 2);
                gs = agg + (size_t)(m0 + r) * FDIM + c * BK + c4 * 4;
            } else {
                int e = idx - 1024;
                int r = e >> 3, c4 = e & 7;
                sd = sbase + (uint32_t)(MT * RS * 4) + (uint32_t)((r * RS + c4 * 4) << 2);
                gs = Wt + (size_t)(n0 + r) * FDIM + c * BK + c4 * 4;
            }
            cp_async16(sd, gs);
        }
        CP_COMMIT();
    };

    issue_chunk(0, 0);

    #pragma unroll 1
    for (int c = 0; c < NCHUNK; c++) {
        const int stage = c & 1;
        if (c + 1 < NCHUNK) {
            issue_chunk(c + 1, (c + 1) & 1);
            CP_WAIT(1);          // chunk c complete
        } else {
            CP_WAIT(0);
        }
        __syncthreads();

        const uint32_t aS = aAddrBase + (uint32_t)(stage * STAGE_FLOATS * 4);
        const uint32_t bS = bAddrBase + (uint32_t)(stage * STAGE_FLOATS * 4);

        #pragma unroll
        for (int ks = 0; ks < 4; ks++) {
            uint32_t afr[2][4];
            #pragma unroll
            for (int tm = 0; tm < 2; tm++)
                ldsm_x4(afr[tm], aS + (uint32_t)((tm * 16 * RS + ks * 8) << 2));

            uint32_t bfr[2][4];
            #pragma unroll
            for (int jj = 0; jj < 2; jj++)
                ldsm_x4(bfr[jj], bS + (uint32_t)((jj * 16 * RS + ks * 8) << 2));

            #pragma unroll
            for (int tm = 0; tm < 2; tm++)
                #pragma unroll
                for (int j = 0; j < 4; j++)
                    mma_tf32(acc[tm][j], afr[tm], bfr[j >> 1][(j & 1) * 2],
                             bfr[j >> 1][(j & 1) * 2 + 1]);
        }
        __syncthreads();       // all warps done reading this stage
    }

    // ---- epilogue: stage accumulators to smem, then coalesced store ----
    {
        float* ep = sm_dyn;
        #pragma unroll
        for (int tm = 0; tm < 2; tm++) {
            int rbase = wm * 32 + tm * 16 + (lid >> 2);
            int cbase = wn * 32 + (lid & 3) * 2;
            #pragma unroll
            for (int j = 0; j < 4; j++) {
                float2 lo = make_float2(acc[tm][j][0], acc[tm][j][1]);
                float2 hi = make_float2(acc[tm][j][2], acc[tm][j][3]);
                *reinterpret_cast<float2*>(&ep[rbase * EPS + cbase + j * 8])       = lo;
                *reinterpret_cast<float2*>(&ep[(rbase + 8) * EPS + cbase + j * 8]) = hi;
            }
        }
        __syncthreads();

        const float4* f4 = reinterpret_cast<const float4*>(feats);
        float4* o4 = reinterpret_cast<float4*>(out);
        const float4* b4 = reinterpret_cast<const float4*>(bias);
        #pragma unroll
        for (int it = 0; it < 8; it++) {
            int lin = it * 256 + t;          // 0..2047
            int r   = lin >> 4;              // 0..127
            int c4  = lin & 15;              // 0..15 float4s (64 cols)
            float4 v = *reinterpret_cast<const float4*>(&ep[r * EPS + c4 * 4]);
            float4 bb = __ldg(&b4[(n0 >> 2) + c4]);
            size_t gi = ((size_t)(m0 + r) * FDIM + n0) / 4 + c4;
            float4 ff = __ldg(&f4[gi]);
            v.x = fmaxf(v.x + bb.x, 0.f) + ff.x;
            v.y = fmaxf(v.y + bb.y, 0.f) + ff.y;
            v.z = fmaxf(v.z + bb.z, 0.f) + ff.z;
            v.w = fmaxf(v.w + bb.w, 0.f) + ff.w;
            o4[gi] = v;
        }
    }
}

// ---------------------------------------------------------------------------
extern "C" void kernel_launch(void* const* d_in, const int* in_sizes, int n_in,
                              void* d_out, int out_size)
{
    const float* A     = (const float*)d_in[0];  // [16,8,400,400]
    const float* feats = (const float*)d_in[1];  // [16,8,400,256]
    const float* W     = (const float*)d_in[2];  // [256,256]
    const float* bias  = (const float*)d_in[3];  // [256]
    float* out = (float*)d_out;

    float* agg;  cudaGetSymbolAddress((void**)&agg, g_agg);
    float* Wt;   cudaGetSymbolAddress((void**)&Wt,  g_Wt);

    static bool attr_set = false;
    if (!attr_set) {
        cudaFuncSetAttribute(gemm_tf32_kernel,
                             cudaFuncAttributeMaxDynamicSharedMemorySize,
                             SMEM_FLOATS * 4);
        attr_set = true;
    }

    // 3200 mask blocks (16 rows each) + 64 W-conversion blocks
    mask_agg_kernel<<<NROWS / 16 + 64, 256>>>(A, feats, W, Wt, agg);

    // grid: x = N tiles (fast) so agg-tile-sharing CTAs are bid-adjacent
    dim3 grid(FDIM / NT, NROWS / MT);   // (4, 400)
    gemm_tf32_kernel<<<grid, 256, SMEM_FLOATS * 4>>>(agg, Wt, bias, feats, out);
}